// round 14
// baseline (speedup 1.0000x reference)
#include <cuda_runtime.h>
#include <cuda_fp16.h>
#include <math.h>

// Problem constants
#define BATCH 4
#define IMH 1080
#define IMW 1920
#define PLANE (IMH*IMW)          // 2073600
#define Q4 (PLANE/4)             // 518400
#define Q8 (PLANE/8)             // 259200
#define TH 256                   // thumbnail size
#define S 33
#define S3 (S*S*S)               // 35937

// Scratch (device globals; allocation is forbidden)
__device__ float g_tmpW[BATCH*3*IMH*TH];     // after W-resize  [b,c,1080,256]
__device__ float g_thumb[BATCH*3*TH*TH];     // [b,c,256,256]
__device__ float g_a1[BATCH*16*128*128];
__device__ float g_a2[BATCH*32*64*64];
__device__ float g_pooled[BATCH*32];
// padded weights: each 9-float group padded to 12 for LDS.128
__device__ __align__(16) float g_w1p[48*12];    // conv1: (co*3+ci)*12
__device__ __align__(16) float g_w2p[512*12];   // conv2: (co*16+ci)*12
// packed LUT cell: ALL 8 trilinear corners of cell (z,y,x):
//   u[0..5]  = fp16 xy-quad at z   {rgb@(x,y), rgb@(x+1,y), rgb@(x,y+1), rgb@(x+1,y+1)}
//   u[8..13] = fp16 xy-quad at z+1 (same order)
// 64B aligned -> both 32B halves live in ONE 128B L1 line.
struct __align__(64) LutCell { unsigned int u[16]; };
__device__ LutCell g_lutc[BATCH*S3];

// 256-bit non-coherent global load (Blackwell LDG.E.256), raw b32
__device__ __forceinline__ void ldg256u(const void* __restrict__ p, unsigned int* o) {
    asm volatile("ld.global.nc.v8.b32 {%0,%1,%2,%3,%4,%5,%6,%7}, [%8];"
                 : "=r"(o[0]), "=r"(o[1]), "=r"(o[2]), "=r"(o[3]),
                   "=r"(o[4]), "=r"(o[5]), "=r"(o[6]), "=r"(o[7])
                 : "l"(p));
}

// ---------------------------------------------------------------------------
// 0) pad conv weights 9 -> 12 per group (once; enables float4 staging in convs)
// ---------------------------------------------------------------------------
__global__ void k_pad_w(const float* __restrict__ w1, const float* __restrict__ w2) {
    int t = blockIdx.x * blockDim.x + threadIdx.x;
    if (t < 432)  { int g = t/9, k = t - g*9; g_w1p[g*12 + k] = w1[t]; }
    if (t < 4608) { int g = t/9, k = t - g*9; g_w2p[g*12 + k] = w2[t]; }
}

// ---------------------------------------------------------------------------
// 1) separable antialiased triangle resize, W: 1920 -> 256  (inv_scale = 7.5)
// ---------------------------------------------------------------------------
__global__ void k_resize_w(const float* __restrict__ img) {
    __shared__ __align__(16) float srow[IMW];
    int row = blockIdx.x;                      // 0 .. 4*3*1080-1
    const float4* src = (const float4*)(img + (size_t)row * IMW);
    for (int i = threadIdx.x; i < IMW/4; i += 256)
        ((float4*)srow)[i] = src[i];
    __syncthreads();
    int ow = threadIdx.x;
    const float INV = 7.5f;
    float sf = (ow + 0.5f) * INV - 0.5f;
    int jlo = (int)ceilf(sf - INV); if (jlo < 0) jlo = 0;
    int jhi = (int)floorf(sf + INV); if (jhi > IMW-1) jhi = IMW-1;
    float acc = 0.f, wsum = 0.f;
    for (int j = jlo; j <= jhi; j++) {
        float w = 1.0f - fabsf(sf - (float)j) * (1.0f/INV);
        if (w > 0.f) { acc += w * srow[j]; wsum += w; }
    }
    g_tmpW[(size_t)row * TH + ow] = acc / wsum;
}

// H: 1080 -> 256  (inv_scale = 4.21875)
__global__ void k_resize_h() {
    int t = blockIdx.x * blockDim.x + threadIdx.x;
    if (t >= BATCH*3*TH*TH) return;
    int ow = t & 255;
    int oh = (t >> 8) & 255;
    int bc = t >> 16;
    const float INV = 4.21875f;
    float sf = (oh + 0.5f) * INV - 0.5f;
    int jlo = (int)ceilf(sf - INV); if (jlo < 0) jlo = 0;
    int jhi = (int)floorf(sf + INV); if (jhi > IMH-1) jhi = IMH-1;
    float acc = 0.f, wsum = 0.f;
    const float* col = g_tmpW + (size_t)bc * IMH * TH + ow;
    for (int j = jlo; j <= jhi; j++) {
        float w = 1.0f - fabsf(sf - (float)j) * (1.0f/INV);
        if (w > 0.f) { acc += w * col[j * TH]; wsum += w; }
    }
    g_thumb[t] = acc / wsum;
}

// ---------------------------------------------------------------------------
// 2) conv1: [b,3,256,256] -> relu -> [b,16,128,128], stride 2, pad (0,1)
//    grid = B*256 (8x8 output tiles), 256 threads = 64 spatial x 4 co-groups of 4
// ---------------------------------------------------------------------------
#define C1_STR 18
#define C1_CI  (17*C1_STR)   // 306
__global__ __launch_bounds__(256) void k_conv1(const float* __restrict__ bias) {
    __shared__ __align__(16) float sW[48*12];
    __shared__ __align__(16) float sIn[3*C1_CI];   // 918
    __shared__ float sB[16];
    int blk = blockIdx.x;
    int b = blk >> 8, tile = blk & 255;
    int oy0 = (tile >> 4) * 8, ox0 = (tile & 15) * 8;
    int tid = threadIdx.x;
    if (tid < 144) ((float4*)sW)[tid] = ((const float4*)g_w1p)[tid];
    if (tid < 16) sB[tid] = bias[tid];
    const float* src = g_thumb + (size_t)b * 3 * TH * TH;
    for (int i = tid; i < 3*289; i += 256) {
        int ci = i / 289, r = i - ci*289;
        int dy = r / 17, dx = r - dy*17;
        int iy = 2*oy0 + dy, ix = 2*ox0 + dx;
        sIn[ci*C1_CI + dy*C1_STR + dx] =
            (iy < TH && ix < TH) ? src[(size_t)ci*TH*TH + iy*TH + ix] : 0.f;
    }
    __syncthreads();
    int sp = tid & 63, cog = tid >> 6;       // 4 co-groups of 4
    int ly = sp >> 3, lx = sp & 7;
    int oy = oy0 + ly, ox = ox0 + lx;
    float acc[4];
    #pragma unroll
    for (int i = 0; i < 4; i++) acc[i] = 0.f;
    #pragma unroll
    for (int ci = 0; ci < 3; ci++) {
        float v[9];
        #pragma unroll
        for (int kh = 0; kh < 3; kh++) {
            int base = ci*C1_CI + (2*ly + kh)*C1_STR + 2*lx;   // even -> 8B aligned
            float2 p = *(const float2*)&sIn[base];
            v[kh*3+0] = p.x; v[kh*3+1] = p.y; v[kh*3+2] = sIn[base+2];
        }
        #pragma unroll
        for (int i = 0; i < 4; i++) {
            int co = cog*4 + i;
            const float4* wp = (const float4*)&sW[(co*3 + ci)*12];
            float4 wa = wp[0], wb = wp[1], wc = wp[2];
            float a = acc[i];
            a += v[0]*wa.x + v[1]*wa.y + v[2]*wa.z + v[3]*wa.w;
            a += v[4]*wb.x + v[5]*wb.y + v[6]*wb.z + v[7]*wb.w;
            a += v[8]*wc.x;
            acc[i] = a;
        }
    }
    #pragma unroll
    for (int i = 0; i < 4; i++) {
        int co = cog*4 + i;
        float r = acc[i] + sB[co];
        r = r > 0.f ? r : 0.f;
        g_a1[(((size_t)b*16 + co)*128 + oy)*128 + ox] = r;
    }
}

// conv2: [b,16,128,128] -> relu -> [b,32,64,64]
#define C2_STR 10
#define C2_CI  (9*C2_STR)    // 90
__global__ __launch_bounds__(256) void k_conv2(const float* __restrict__ bias) {
    __shared__ __align__(16) float sW[512*12];     // 6144 floats
    __shared__ __align__(16) float sIn[16*C2_CI];  // 1440
    __shared__ float sB[32];
    int blk = blockIdx.x;
    int b = blk >> 8, tile = blk & 255;
    int oy0 = (tile >> 4) * 4, ox0 = (tile & 15) * 4;
    int tid = threadIdx.x;
    #pragma unroll
    for (int i = 0; i < 6; i++)
        ((float4*)sW)[tid + i*256] = ((const float4*)g_w2p)[tid + i*256];
    if (tid < 32) sB[tid] = bias[tid];
    const float* src = g_a1 + (size_t)b * 16 * 128 * 128;
    for (int i = tid; i < 16*81; i += 256) {
        int ci = i / 81, r = i - ci*81;
        int dy = r / 9, dx = r - dy*9;
        int iy = 2*oy0 + dy, ix = 2*ox0 + dx;
        sIn[ci*C2_CI + dy*C2_STR + dx] =
            (iy < 128 && ix < 128) ? src[(size_t)ci*128*128 + iy*128 + ix] : 0.f;
    }
    __syncthreads();
    int sp = tid & 15, cog = tid >> 4;       // 16 co-groups of 2
    int ly = sp >> 2, lx = sp & 3;
    int oy = oy0 + ly, ox = ox0 + lx;
    float acc[2];
    acc[0] = 0.f; acc[1] = 0.f;
    #pragma unroll
    for (int ci = 0; ci < 16; ci++) {
        float v[9];
        #pragma unroll
        for (int kh = 0; kh < 3; kh++) {
            int base = ci*C2_CI + (2*ly + kh)*C2_STR + 2*lx;   // even -> 8B aligned
            float2 p = *(const float2*)&sIn[base];
            v[kh*3+0] = p.x; v[kh*3+1] = p.y; v[kh*3+2] = sIn[base+2];
        }
        #pragma unroll
        for (int i = 0; i < 2; i++) {
            int co = cog*2 + i;
            const float4* wp = (const float4*)&sW[(co*16 + ci)*12];
            float4 wa = wp[0], wb = wp[1], wc = wp[2];
            float a = acc[i];
            a += v[0]*wa.x + v[1]*wa.y + v[2]*wa.z + v[3]*wa.w;
            a += v[4]*wb.x + v[5]*wb.y + v[6]*wb.z + v[7]*wb.w;
            a += v[8]*wc.x;
            acc[i] = a;
        }
    }
    #pragma unroll
    for (int i = 0; i < 2; i++) {
        int co = cog*2 + i;
        float r = acc[i] + sB[co];
        r = r > 0.f ? r : 0.f;
        g_a2[(((size_t)b*32 + co)*64 + oy)*64 + ox] = r;
    }
}

// global average pool: one block per (b,c)
__global__ void k_gap() {
    __shared__ float red[256];
    int bc = blockIdx.x;
    const float* src = g_a2 + (size_t)bc * 4096;
    float s = 0.f;
    for (int i = threadIdx.x; i < 4096; i += 256) s += src[i];
    red[threadIdx.x] = s;
    __syncthreads();
    for (int st = 128; st > 0; st >>= 1) {
        if (threadIdx.x < st) red[threadIdx.x] += red[threadIdx.x + st];
        __syncthreads();
    }
    if (threadIdx.x == 0) g_pooled[bc] = red[0] * (1.0f/4096.0f);
}

// blend basis LUTs -> fp16 z-pair cell LUT; dense+softmax fused
__device__ __forceinline__ float3 blend3(const float* __restrict__ basis,
                                         float w0, float w1, float w2, int p) {
    const float* a0 = basis + (size_t)p * 3;
    const float* a1 = a0 + (size_t)S3 * 3;
    const float* a2 = a1 + (size_t)S3 * 3;
    return make_float3(w0*a0[0] + w1*a1[0] + w2*a2[0],
                       w0*a0[1] + w1*a1[1] + w2*a2[1],
                       w0*a0[2] + w1*a1[2] + w2*a2[2]);
}

__device__ __forceinline__ void pack_quad(const float* __restrict__ basis,
                                          float w0, float w1, float w2,
                                          int p, int dx, int dy,
                                          unsigned int* u) {
    float3 c00 = blend3(basis, w0, w1, w2, p);
    float3 c10 = blend3(basis, w0, w1, w2, p + dx);
    float3 c01 = blend3(basis, w0, w1, w2, p + dy);
    float3 c11 = blend3(basis, w0, w1, w2, p + dy + dx);
    __half2 h0 = __floats2half2_rn(c00.x, c00.y);
    __half2 h1 = __floats2half2_rn(c00.z, c10.x);
    __half2 h2 = __floats2half2_rn(c10.y, c10.z);
    __half2 h3 = __floats2half2_rn(c01.x, c01.y);
    __half2 h4 = __floats2half2_rn(c01.z, c11.x);
    __half2 h5 = __floats2half2_rn(c11.y, c11.z);
    u[0] = *(unsigned int*)&h0;
    u[1] = *(unsigned int*)&h1;
    u[2] = *(unsigned int*)&h2;
    u[3] = *(unsigned int*)&h3;
    u[4] = *(unsigned int*)&h4;
    u[5] = *(unsigned int*)&h5;
    u[6] = 0u; u[7] = 0u;
}

__global__ void k_blend(const float* __restrict__ basis,
                        const float* __restrict__ dw, const float* __restrict__ db) {
    int t = blockIdx.x * blockDim.x + threadIdx.x;
    if (t >= BATCH * S3) return;
    int b = t / S3, p = t - b * S3;
    // fused dense + softmax (reads 32 pooled floats, all L1/L2-hot)
    float l[3];
    #pragma unroll
    for (int k = 0; k < 3; k++) {
        float a = __ldg(db + k);
        #pragma unroll 8
        for (int c = 0; c < 32; c++) a += __ldg(&g_pooled[b*32 + c]) * __ldg(&dw[c*3 + k]);
        l[k] = a;
    }
    float m = fmaxf(l[0], fmaxf(l[1], l[2]));
    float e0 = expf(l[0]-m), e1 = expf(l[1]-m), e2 = expf(l[2]-m);
    float inv = 1.0f / (e0 + e1 + e2);
    float w0 = e0*inv, w1 = e1*inv, w2 = e2*inv;

    int x = p % S;
    int y = (p / S) % S;
    int z = p / (S*S);
    int dx = (x < S-1) ? 1 : 0;
    int dy = (y < S-1) ? S : 0;
    int dz = (z < S-1) ? S*S : 0;
    unsigned int cell[16];
    pack_quad(basis, w0, w1, w2, p,      dx, dy, cell);       // z plane
    pack_quad(basis, w0, w1, w2, p + dz, dx, dy, cell + 8);   // z+1 plane
    uint4* dst = (uint4*)&g_lutc[t];
    dst[0] = make_uint4(cell[0],  cell[1],  cell[2],  cell[3]);
    dst[1] = make_uint4(cell[4],  cell[5],  cell[6],  cell[7]);
    dst[2] = make_uint4(cell[8],  cell[9],  cell[10], cell[11]);
    dst[3] = make_uint4(cell[12], cell[13], cell[14], cell[15]);
}

// ---------------------------------------------------------------------------
// 3) trilinear LUT apply; ONE 128B line per pixel (both 32B halves of one cell)
// ---------------------------------------------------------------------------
__device__ __forceinline__ float3 quad_bilerp(const unsigned int* u, float fx, float fy) {
    float2 f0 = __half22float2(*(const __half2*)&u[0]);  // r00 g00
    float2 f1 = __half22float2(*(const __half2*)&u[1]);  // b00 r10
    float2 f2 = __half22float2(*(const __half2*)&u[2]);  // g10 b10
    float2 f3 = __half22float2(*(const __half2*)&u[3]);  // r01 g01
    float2 f4 = __half22float2(*(const __half2*)&u[4]);  // b01 r11
    float2 f5 = __half22float2(*(const __half2*)&u[5]);  // g11 b11
    float gx = 1.f - fx, gy = 1.f - fy;
    float w00 = gy*gx, w10 = gy*fx, w01 = fy*gx, w11 = fy*fx;
    return make_float3(w00*f0.x + w10*f1.y + w01*f3.x + w11*f4.y,
                       w00*f0.y + w10*f2.x + w01*f3.y + w11*f5.x,
                       w00*f1.x + w10*f2.y + w01*f4.x + w11*f5.y);
}

__device__ __forceinline__ void lut_one(const LutCell* __restrict__ lut,
                                        float r, float g, float b,
                                        float& orr, float& org, float& orb) {
    float px = fminf(fmaxf(r, 0.f), 1.f) * 32.f;   // x <- R
    float py = fminf(fmaxf(g, 0.f), 1.f) * 32.f;   // y <- G
    float pz = fminf(fmaxf(b, 0.f), 1.f) * 32.f;   // z <- B
    int x0 = min((int)px, 31);
    int y0 = min((int)py, 31);
    int z0 = min((int)pz, 31);
    float fx = px - (float)x0, fy = py - (float)y0, fz = pz - (float)z0;
    const LutCell* cell = lut + (z0*S + y0)*S + x0;
    unsigned int q0[8], q1[8];
    ldg256u(cell, q0);                               // z plane quad
    ldg256u((const char*)cell + 32, q1);             // z+1 plane quad (same L1 line)
    float3 v0 = quad_bilerp(q0, fx, fy);
    float3 v1 = quad_bilerp(q1, fx, fy);
    float gz = 1.f - fz;
    orr = fminf(fmaxf(gz*v0.x + fz*v1.x, 0.f), 1.f);
    org = fminf(fmaxf(gz*v0.y + fz*v1.y, 0.f), 1.f);
    orb = fminf(fmaxf(gz*v0.z + fz*v1.z, 0.f), 1.f);
}

__global__ __launch_bounds__(256) void k_apply(const float* __restrict__ img,
                                               float* __restrict__ out) {
    int t = blockIdx.x * blockDim.x + threadIdx.x;
    if (t >= BATCH * Q8) return;
    int b = t / Q8;
    int off8 = t - b * Q8;
    const LutCell* lut = g_lutc + (size_t)b * S3;
    const float4* pr = (const float4*)(img + (size_t)b * 3 * PLANE) + off8*2;
    float4* po = (float4*)(out + (size_t)b * 3 * PLANE) + off8*2;
    #pragma unroll
    for (int h = 0; h < 2; h++) {
        float4 R  = __ldg(pr + h);
        float4 G  = __ldg(pr + Q4 + h);
        float4 Bc = __ldg(pr + 2*Q4 + h);
        float rr[4] = {R.x, R.y, R.z, R.w};
        float gg[4] = {G.x, G.y, G.z, G.w};
        float bb[4] = {Bc.x, Bc.y, Bc.z, Bc.w};
        float orr[4], org[4], orb[4];
        #pragma unroll
        for (int i = 0; i < 4; i++)
            lut_one(lut, rr[i], gg[i], bb[i], orr[i], org[i], orb[i]);
        po[h]        = make_float4(orr[0], orr[1], orr[2], orr[3]);
        po[Q4 + h]   = make_float4(org[0], org[1], org[2], org[3]);
        po[2*Q4 + h] = make_float4(orb[0], orb[1], orb[2], orb[3]);
    }
}

// ---------------------------------------------------------------------------
extern "C" void kernel_launch(void* const* d_in, const int* in_sizes, int n_in,
                              void* d_out, int out_size) {
    const float* image   = (const float*)d_in[0];
    const float* basis   = (const float*)d_in[1];
    const float* conv1_w = (const float*)d_in[2];
    const float* conv1_b = (const float*)d_in[3];
    const float* conv2_w = (const float*)d_in[4];
    const float* conv2_b = (const float*)d_in[5];
    const float* dense_w = (const float*)d_in[6];
    const float* dense_b = (const float*)d_in[7];
    float* out = (float*)d_out;

    k_pad_w<<<18, 256>>>(conv1_w, conv2_w);
    k_resize_w<<<BATCH*3*IMH, 256>>>(image);
    k_resize_h<<<(BATCH*3*TH*TH + 255)/256, 256>>>();
    k_conv1<<<BATCH*256, 256>>>(conv1_b);
    k_conv2<<<BATCH*256, 256>>>(conv2_b);
    k_gap<<<BATCH*32, 256>>>();
    k_blend<<<(BATCH*S3 + 255)/256, 256>>>(basis, dense_w, dense_b);
    k_apply<<<(BATCH*Q8 + 255)/256, 256>>>(image, out);
}

// round 16
// speedup vs baseline: 1.2348x; 1.2348x over previous
#include <cuda_runtime.h>
#include <cuda_fp16.h>
#include <math.h>

// Problem constants
#define BATCH 4
#define IMH 1080
#define IMW 1920
#define PLANE (IMH*IMW)          // 2073600
#define Q4 (PLANE/4)             // 518400
#define Q8 (PLANE/8)             // 259200
#define TH 256                   // thumbnail size
#define S 33
#define S3 (S*S*S)               // 35937

// 10-bit fixed-point LUT encoding over [-0.25, 1.25]
#define QSCALE 682.0f            // 1023/1.5
#define DSCALE (1.5f/1023.0f)
#define DOFF   (-0.25f)

// Scratch (device globals; allocation is forbidden)
__device__ float g_tmpW[BATCH*3*IMH*TH];     // after W-resize  [b,c,1080,256]
__device__ float g_thumb[BATCH*3*TH*TH];     // [b,c,256,256]
__device__ float g_a1[BATCH*16*128*128];
__device__ float g_a2[BATCH*32*64*64];
__device__ float g_pooled[BATCH*32];
// padded weights: each 9-float group padded to 12 for LDS.128
__device__ __align__(16) float g_w1p[48*12];    // conv1: (co*3+ci)*12
__device__ __align__(16) float g_w2p[512*12];   // conv2: (co*16+ci)*12
// packed LUT cell: ALL 8 trilinear corners, 10-bit fixed (r|g<<10|b<<20) per corner
// word k = corner (dx,dy,dz), k = dx + 2*dy + 4*dz.  ONE LDG.256 per pixel.
struct __align__(32) LutCell { unsigned int u[8]; };
__device__ LutCell g_lutc[BATCH*S3];

// 256-bit non-coherent global load (Blackwell LDG.E.256), raw b32
__device__ __forceinline__ void ldg256u(const void* __restrict__ p, unsigned int* o) {
    asm volatile("ld.global.nc.v8.b32 {%0,%1,%2,%3,%4,%5,%6,%7}, [%8];"
                 : "=r"(o[0]), "=r"(o[1]), "=r"(o[2]), "=r"(o[3]),
                   "=r"(o[4]), "=r"(o[5]), "=r"(o[6]), "=r"(o[7])
                 : "l"(p));
}

// ---------------------------------------------------------------------------
// 0) pad conv weights 9 -> 12 per group (once; enables float4 staging in convs)
// ---------------------------------------------------------------------------
__global__ void k_pad_w(const float* __restrict__ w1, const float* __restrict__ w2) {
    int t = blockIdx.x * blockDim.x + threadIdx.x;
    if (t < 432)  { int g = t/9, k = t - g*9; g_w1p[g*12 + k] = w1[t]; }
    if (t < 4608) { int g = t/9, k = t - g*9; g_w2p[g*12 + k] = w2[t]; }
}

// ---------------------------------------------------------------------------
// 1) separable antialiased triangle resize, W: 1920 -> 256  (inv_scale = 7.5)
// ---------------------------------------------------------------------------
__global__ void k_resize_w(const float* __restrict__ img) {
    __shared__ __align__(16) float srow[IMW];
    int row = blockIdx.x;                      // 0 .. 4*3*1080-1
    const float4* src = (const float4*)(img + (size_t)row * IMW);
    for (int i = threadIdx.x; i < IMW/4; i += 256)
        ((float4*)srow)[i] = src[i];
    __syncthreads();
    int ow = threadIdx.x;
    const float INV = 7.5f;
    float sf = (ow + 0.5f) * INV - 0.5f;
    int jlo = (int)ceilf(sf - INV); if (jlo < 0) jlo = 0;
    int jhi = (int)floorf(sf + INV); if (jhi > IMW-1) jhi = IMW-1;
    float acc = 0.f, wsum = 0.f;
    for (int j = jlo; j <= jhi; j++) {
        float w = 1.0f - fabsf(sf - (float)j) * (1.0f/INV);
        if (w > 0.f) { acc += w * srow[j]; wsum += w; }
    }
    g_tmpW[(size_t)row * TH + ow] = acc / wsum;
}

// H: 1080 -> 256  (inv_scale = 4.21875)
__global__ void k_resize_h() {
    int t = blockIdx.x * blockDim.x + threadIdx.x;
    if (t >= BATCH*3*TH*TH) return;
    int ow = t & 255;
    int oh = (t >> 8) & 255;
    int bc = t >> 16;
    const float INV = 4.21875f;
    float sf = (oh + 0.5f) * INV - 0.5f;
    int jlo = (int)ceilf(sf - INV); if (jlo < 0) jlo = 0;
    int jhi = (int)floorf(sf + INV); if (jhi > IMH-1) jhi = IMH-1;
    float acc = 0.f, wsum = 0.f;
    const float* col = g_tmpW + (size_t)bc * IMH * TH + ow;
    for (int j = jlo; j <= jhi; j++) {
        float w = 1.0f - fabsf(sf - (float)j) * (1.0f/INV);
        if (w > 0.f) { acc += w * col[j * TH]; wsum += w; }
    }
    g_thumb[t] = acc / wsum;
}

// ---------------------------------------------------------------------------
// 2) conv1: [b,3,256,256] -> relu -> [b,16,128,128], stride 2, pad (0,1)
// ---------------------------------------------------------------------------
#define C1_STR 18
#define C1_CI  (17*C1_STR)   // 306
__global__ __launch_bounds__(256) void k_conv1(const float* __restrict__ bias) {
    __shared__ __align__(16) float sW[48*12];
    __shared__ __align__(16) float sIn[3*C1_CI];   // 918
    __shared__ float sB[16];
    int blk = blockIdx.x;
    int b = blk >> 8, tile = blk & 255;
    int oy0 = (tile >> 4) * 8, ox0 = (tile & 15) * 8;
    int tid = threadIdx.x;
    if (tid < 144) ((float4*)sW)[tid] = ((const float4*)g_w1p)[tid];
    if (tid < 16) sB[tid] = bias[tid];
    const float* src = g_thumb + (size_t)b * 3 * TH * TH;
    for (int i = tid; i < 3*289; i += 256) {
        int ci = i / 289, r = i - ci*289;
        int dy = r / 17, dx = r - dy*17;
        int iy = 2*oy0 + dy, ix = 2*ox0 + dx;
        sIn[ci*C1_CI + dy*C1_STR + dx] =
            (iy < TH && ix < TH) ? src[(size_t)ci*TH*TH + iy*TH + ix] : 0.f;
    }
    __syncthreads();
    int sp = tid & 63, cog = tid >> 6;       // 4 co-groups of 4
    int ly = sp >> 3, lx = sp & 7;
    int oy = oy0 + ly, ox = ox0 + lx;
    float acc[4];
    #pragma unroll
    for (int i = 0; i < 4; i++) acc[i] = 0.f;
    #pragma unroll
    for (int ci = 0; ci < 3; ci++) {
        float v[9];
        #pragma unroll
        for (int kh = 0; kh < 3; kh++) {
            int base = ci*C1_CI + (2*ly + kh)*C1_STR + 2*lx;   // even -> 8B aligned
            float2 p = *(const float2*)&sIn[base];
            v[kh*3+0] = p.x; v[kh*3+1] = p.y; v[kh*3+2] = sIn[base+2];
        }
        #pragma unroll
        for (int i = 0; i < 4; i++) {
            int co = cog*4 + i;
            const float4* wp = (const float4*)&sW[(co*3 + ci)*12];
            float4 wa = wp[0], wb = wp[1], wc = wp[2];
            float a = acc[i];
            a += v[0]*wa.x + v[1]*wa.y + v[2]*wa.z + v[3]*wa.w;
            a += v[4]*wb.x + v[5]*wb.y + v[6]*wb.z + v[7]*wb.w;
            a += v[8]*wc.x;
            acc[i] = a;
        }
    }
    #pragma unroll
    for (int i = 0; i < 4; i++) {
        int co = cog*4 + i;
        float r = acc[i] + sB[co];
        r = r > 0.f ? r : 0.f;
        g_a1[(((size_t)b*16 + co)*128 + oy)*128 + ox] = r;
    }
}

// conv2: [b,16,128,128] -> relu -> [b,32,64,64]
#define C2_STR 10
#define C2_CI  (9*C2_STR)    // 90
__global__ __launch_bounds__(256) void k_conv2(const float* __restrict__ bias) {
    __shared__ __align__(16) float sW[512*12];     // 6144 floats
    __shared__ __align__(16) float sIn[16*C2_CI];  // 1440
    __shared__ float sB[32];
    int blk = blockIdx.x;
    int b = blk >> 8, tile = blk & 255;
    int oy0 = (tile >> 4) * 4, ox0 = (tile & 15) * 4;
    int tid = threadIdx.x;
    #pragma unroll
    for (int i = 0; i < 6; i++)
        ((float4*)sW)[tid + i*256] = ((const float4*)g_w2p)[tid + i*256];
    if (tid < 32) sB[tid] = bias[tid];
    const float* src = g_a1 + (size_t)b * 16 * 128 * 128;
    for (int i = tid; i < 16*81; i += 256) {
        int ci = i / 81, r = i - ci*81;
        int dy = r / 9, dx = r - dy*9;
        int iy = 2*oy0 + dy, ix = 2*ox0 + dx;
        sIn[ci*C2_CI + dy*C2_STR + dx] =
            (iy < 128 && ix < 128) ? src[(size_t)ci*128*128 + iy*128 + ix] : 0.f;
    }
    __syncthreads();
    int sp = tid & 15, cog = tid >> 4;       // 16 co-groups of 2
    int ly = sp >> 2, lx = sp & 3;
    int oy = oy0 + ly, ox = ox0 + lx;
    float acc[2];
    acc[0] = 0.f; acc[1] = 0.f;
    #pragma unroll
    for (int ci = 0; ci < 16; ci++) {
        float v[9];
        #pragma unroll
        for (int kh = 0; kh < 3; kh++) {
            int base = ci*C2_CI + (2*ly + kh)*C2_STR + 2*lx;   // even -> 8B aligned
            float2 p = *(const float2*)&sIn[base];
            v[kh*3+0] = p.x; v[kh*3+1] = p.y; v[kh*3+2] = sIn[base+2];
        }
        #pragma unroll
        for (int i = 0; i < 2; i++) {
            int co = cog*2 + i;
            const float4* wp = (const float4*)&sW[(co*16 + ci)*12];
            float4 wa = wp[0], wb = wp[1], wc = wp[2];
            float a = acc[i];
            a += v[0]*wa.x + v[1]*wa.y + v[2]*wa.z + v[3]*wa.w;
            a += v[4]*wb.x + v[5]*wb.y + v[6]*wb.z + v[7]*wb.w;
            a += v[8]*wc.x;
            acc[i] = a;
        }
    }
    #pragma unroll
    for (int i = 0; i < 2; i++) {
        int co = cog*2 + i;
        float r = acc[i] + sB[co];
        r = r > 0.f ? r : 0.f;
        g_a2[(((size_t)b*32 + co)*64 + oy)*64 + ox] = r;
    }
}

// global average pool: one block per (b,c)
__global__ void k_gap() {
    __shared__ float red[256];
    int bc = blockIdx.x;
    const float* src = g_a2 + (size_t)bc * 4096;
    float s = 0.f;
    for (int i = threadIdx.x; i < 4096; i += 256) s += src[i];
    red[threadIdx.x] = s;
    __syncthreads();
    for (int st = 128; st > 0; st >>= 1) {
        if (threadIdx.x < st) red[threadIdx.x] += red[threadIdx.x + st];
        __syncthreads();
    }
    if (threadIdx.x == 0) g_pooled[bc] = red[0] * (1.0f/4096.0f);
}

// blend basis LUTs -> 10-bit packed 8-corner cells; dense+softmax fused
__device__ __forceinline__ float3 blend3(const float* __restrict__ basis,
                                         float w0, float w1, float w2, int p) {
    const float* a0 = basis + (size_t)p * 3;
    const float* a1 = a0 + (size_t)S3 * 3;
    const float* a2 = a1 + (size_t)S3 * 3;
    return make_float3(w0*a0[0] + w1*a1[0] + w2*a2[0],
                       w0*a0[1] + w1*a1[1] + w2*a2[1],
                       w0*a0[2] + w1*a1[2] + w2*a2[2]);
}

__device__ __forceinline__ unsigned int q10(float v) {
    int q = __float2int_rn((v - DOFF) * QSCALE);
    return (unsigned int)min(max(q, 0), 1023);
}

__global__ void k_blend(const float* __restrict__ basis,
                        const float* __restrict__ dw, const float* __restrict__ db) {
    int t = blockIdx.x * blockDim.x + threadIdx.x;
    if (t >= BATCH * S3) return;
    int b = t / S3, p = t - b * S3;
    // fused dense + softmax (reads 32 pooled floats, all L1/L2-hot)
    float l[3];
    #pragma unroll
    for (int k = 0; k < 3; k++) {
        float a = __ldg(db + k);
        #pragma unroll 8
        for (int c = 0; c < 32; c++) a += __ldg(&g_pooled[b*32 + c]) * __ldg(&dw[c*3 + k]);
        l[k] = a;
    }
    float m = fmaxf(l[0], fmaxf(l[1], l[2]));
    float e0 = expf(l[0]-m), e1 = expf(l[1]-m), e2 = expf(l[2]-m);
    float inv = 1.0f / (e0 + e1 + e2);
    float w0 = e0*inv, w1 = e1*inv, w2 = e2*inv;

    int x = p % S;
    int y = (p / S) % S;
    int z = p / (S*S);
    int dx = (x < S-1) ? 1 : 0;
    int dy = (y < S-1) ? S : 0;
    int dz = (z < S-1) ? S*S : 0;
    unsigned int u[8];
    #pragma unroll
    for (int k = 0; k < 8; k++) {
        int off = ((k & 1) ? dx : 0) + ((k & 2) ? dy : 0) + ((k & 4) ? dz : 0);
        float3 c = blend3(basis, w0, w1, w2, p + off);
        u[k] = q10(c.x) | (q10(c.y) << 10) | (q10(c.z) << 20);
    }
    uint4* dst = (uint4*)&g_lutc[t];
    dst[0] = make_uint4(u[0], u[1], u[2], u[3]);
    dst[1] = make_uint4(u[4], u[5], u[6], u[7]);
}

// ---------------------------------------------------------------------------
// 3) trilinear LUT apply; ONE LDG.256 gather per pixel (all 8 corners in 32B)
// ---------------------------------------------------------------------------
__device__ __forceinline__ void lut_one(const LutCell* __restrict__ lut,
                                        float r, float g, float b,
                                        float& orr, float& org, float& orb) {
    float px = fminf(fmaxf(r, 0.f), 1.f) * 32.f;   // x <- R
    float py = fminf(fmaxf(g, 0.f), 1.f) * 32.f;   // y <- G
    float pz = fminf(fmaxf(b, 0.f), 1.f) * 32.f;   // z <- B
    int x0 = min((int)px, 31);
    int y0 = min((int)py, 31);
    int z0 = min((int)pz, 31);
    float fx = px - (float)x0, fy = py - (float)y0, fz = pz - (float)z0;
    unsigned int q[8];
    ldg256u(lut + (z0*S + y0)*S + x0, q);
    float gx = 1.f - fx, gy = 1.f - fy, gz = 1.f - fz;
    float a0 = gx*gy, a1 = fx*gy, a2 = gx*fy, a3 = fx*fy;
    float w[8];
    w[0] = a0*gz; w[1] = a1*gz; w[2] = a2*gz; w[3] = a3*gz;
    w[4] = a0*fz; w[5] = a1*fz; w[6] = a2*fz; w[7] = a3*fz;
    float vr = 0.f, vg = 0.f, vb = 0.f;
    #pragma unroll
    for (int k = 0; k < 8; k++) {
        unsigned int qq = q[k];
        vr += w[k] * (float)(qq & 1023u);
        vg += w[k] * (float)((qq >> 10) & 1023u);
        vb += w[k] * (float)(qq >> 20);
    }
    vr = vr * DSCALE + DOFF;
    vg = vg * DSCALE + DOFF;
    vb = vb * DSCALE + DOFF;
    orr = fminf(fmaxf(vr, 0.f), 1.f);
    org = fminf(fmaxf(vg, 0.f), 1.f);
    orb = fminf(fmaxf(vb, 0.f), 1.f);
}

__global__ __launch_bounds__(256) void k_apply(const float* __restrict__ img,
                                               float* __restrict__ out) {
    int t = blockIdx.x * blockDim.x + threadIdx.x;
    if (t >= BATCH * Q8) return;
    int b = t / Q8;
    int off8 = t - b * Q8;
    const LutCell* lut = g_lutc + (size_t)b * S3;
    const float4* pr = (const float4*)(img + (size_t)b * 3 * PLANE) + off8*2;
    float4* po = (float4*)(out + (size_t)b * 3 * PLANE) + off8*2;
    #pragma unroll
    for (int h = 0; h < 2; h++) {
        float4 R  = __ldg(pr + h);
        float4 G  = __ldg(pr + Q4 + h);
        float4 Bc = __ldg(pr + 2*Q4 + h);
        float rr[4] = {R.x, R.y, R.z, R.w};
        float gg[4] = {G.x, G.y, G.z, G.w};
        float bb[4] = {Bc.x, Bc.y, Bc.z, Bc.w};
        float orr[4], org[4], orb[4];
        #pragma unroll
        for (int i = 0; i < 4; i++)
            lut_one(lut, rr[i], gg[i], bb[i], orr[i], org[i], orb[i]);
        po[h]        = make_float4(orr[0], orr[1], orr[2], orr[3]);
        po[Q4 + h]   = make_float4(org[0], org[1], org[2], org[3]);
        po[2*Q4 + h] = make_float4(orb[0], orb[1], orb[2], orb[3]);
    }
}

// ---------------------------------------------------------------------------
extern "C" void kernel_launch(void* const* d_in, const int* in_sizes, int n_in,
                              void* d_out, int out_size) {
    const float* image   = (const float*)d_in[0];
    const float* basis   = (const float*)d_in[1];
    const float* conv1_w = (const float*)d_in[2];
    const float* conv1_b = (const float*)d_in[3];
    const float* conv2_w = (const float*)d_in[4];
    const float* conv2_b = (const float*)d_in[5];
    const float* dense_w = (const float*)d_in[6];
    const float* dense_b = (const float*)d_in[7];
    float* out = (float*)d_out;

    k_pad_w<<<18, 256>>>(conv1_w, conv2_w);
    k_resize_w<<<BATCH*3*IMH, 256>>>(image);
    k_resize_h<<<(BATCH*3*TH*TH + 255)/256, 256>>>();
    k_conv1<<<BATCH*256, 256>>>(conv1_b);
    k_conv2<<<BATCH*256, 256>>>(conv2_b);
    k_gap<<<BATCH*32, 256>>>();
    k_blend<<<(BATCH*S3 + 255)/256, 256>>>(basis, dense_w, dense_b);
    k_apply<<<(BATCH*Q8 + 255)/256, 256>>>(image, out);
}